// round 4
// baseline (speedup 1.0000x reference)
#include <cuda_runtime.h>
#include <math.h>

#define BOUND        1.0f
#define MIN_NEAR     0.2f
#define T_THRESH     1e-4f
#define BG_COLOR     1.0f
#define N_STEPS      128

// Two rays per warp (rays 2w and 2w+1), fully interleaved so every dependent
// shuffle chain (scan, exclusive, butterfly reduction) runs at ILP=2.
// Lane l owns samples 4l..4l+3 of each ray: 1 sigma float4 + 3 rgb float4
// per ray per lane; 8 LDG.128 issued up-front (4KB contiguous per warp).
__global__ __launch_bounds__(256)
void nerf_composite_kernel(const float* __restrict__ rays_o,
                           const float* __restrict__ rays_d,
                           const float* __restrict__ sigmas,
                           const float* __restrict__ rgbs,
                           float* __restrict__ out,
                           int N)
{
    const unsigned FULL = 0xFFFFFFFFu;
    int w = (blockIdx.x * blockDim.x + threadIdx.x) >> 5;
    int lane = threadIdx.x & 31;

    int r0 = 2 * w;
    if (r0 >= N) return;
    int r1 = (r0 + 1 < N) ? (r0 + 1) : r0;   // duplicate if N odd (harmless)

    // ---- 8 vectorized loads, all independent ----
    const float4* sigA = (const float4*)(sigmas + (size_t)r0 * N_STEPS);
    const float4* sigB = (const float4*)(sigmas + (size_t)r1 * N_STEPS);
    const float4* rgbA = (const float4*)(rgbs   + (size_t)r0 * (N_STEPS * 3));
    const float4* rgbB = (const float4*)(rgbs   + (size_t)r1 * (N_STEPS * 3));

    float4 sa = sigA[lane];
    float4 sb = sigB[lane];
    float4 a0 = rgbA[3 * lane + 0], a1 = rgbA[3 * lane + 1], a2 = rgbA[3 * lane + 2];
    float4 b0 = rgbB[3 * lane + 0], b1 = rgbB[3 * lane + 1], b2 = rgbB[3 * lane + 2];

    // ---- slab tests for both rays (independent chains, overlap the loads) ----
    float oxA = rays_o[3 * r0 + 0], oyA = rays_o[3 * r0 + 1], ozA = rays_o[3 * r0 + 2];
    float dxA = rays_d[3 * r0 + 0], dyA = rays_d[3 * r0 + 1], dzA = rays_d[3 * r0 + 2];
    float oxB = rays_o[3 * r1 + 0], oyB = rays_o[3 * r1 + 1], ozB = rays_o[3 * r1 + 2];
    float dxB = rays_d[3 * r1 + 0], dyB = rays_d[3 * r1 + 1], dzB = rays_d[3 * r1 + 2];

    if (fabsf(dxA) < 1e-8f) dxA = 1e-8f;
    if (fabsf(dyA) < 1e-8f) dyA = 1e-8f;
    if (fabsf(dzA) < 1e-8f) dzA = 1e-8f;
    if (fabsf(dxB) < 1e-8f) dxB = 1e-8f;
    if (fabsf(dyB) < 1e-8f) dyB = 1e-8f;
    if (fabsf(dzB) < 1e-8f) dzB = 1e-8f;

    float ixA = 1.0f / dxA, iyA = 1.0f / dyA, izA = 1.0f / dzA;
    float ixB = 1.0f / dxB, iyB = 1.0f / dyB, izB = 1.0f / dzB;

    float t1xA = (-BOUND - oxA) * ixA, t2xA = (BOUND - oxA) * ixA;
    float t1yA = (-BOUND - oyA) * iyA, t2yA = (BOUND - oyA) * iyA;
    float t1zA = (-BOUND - ozA) * izA, t2zA = (BOUND - ozA) * izA;
    float t1xB = (-BOUND - oxB) * ixB, t2xB = (BOUND - oxB) * ixB;
    float t1yB = (-BOUND - oyB) * iyB, t2yB = (BOUND - oyB) * iyB;
    float t1zB = (-BOUND - ozB) * izB, t2zB = (BOUND - ozB) * izB;

    float nearA = fmaxf(fmaxf(fminf(t1xA, t2xA), fminf(t1yA, t2yA)), fminf(t1zA, t2zA));
    float farA  = fminf(fminf(fmaxf(t1xA, t2xA), fmaxf(t1yA, t2yA)), fmaxf(t1zA, t2zA));
    float nearB = fmaxf(fmaxf(fminf(t1xB, t2xB), fminf(t1yB, t2yB)), fminf(t1zB, t2zB));
    float farB  = fminf(fminf(fmaxf(t1xB, t2xB), fmaxf(t1yB, t2yB)), fmaxf(t1zB, t2zB));

    nearA = fmaxf(nearA, MIN_NEAR);  farA = fmaxf(farA, nearA + 1e-4f);
    nearB = fmaxf(nearB, MIN_NEAR);  farB = fmaxf(farB, nearB + 1e-4f);

    const float dA = (farA - nearA) * (1.0f / (float)N_STEPS);
    const float dB = (farB - nearB) * (1.0f / (float)N_STEPS);

    // ---- alphas & survival (8 MUFU, independent) ----
    float eA0 = __expf(-sa.x * dA), eA1 = __expf(-sa.y * dA);
    float eA2 = __expf(-sa.z * dA), eA3 = __expf(-sa.w * dA);
    float eB0 = __expf(-sb.x * dB), eB1 = __expf(-sb.y * dB);
    float eB2 = __expf(-sb.z * dB), eB3 = __expf(-sb.w * dB);

    float aA0 = 1.0f - eA0, aA1 = 1.0f - eA1, aA2 = 1.0f - eA2, aA3 = 1.0f - eA3;
    float aB0 = 1.0f - eB0, aB1 = 1.0f - eB1, aB2 = 1.0f - eB2, aB3 = 1.0f - eB3;

    float vA0 = eA0 + 1e-10f, vA1 = eA1 + 1e-10f, vA2 = eA2 + 1e-10f, vA3 = eA3 + 1e-10f;
    float vB0 = eB0 + 1e-10f, vB1 = eB1 + 1e-10f, vB2 = eB2 + 1e-10f, vB3 = eB3 + 1e-10f;

    // lane-local prefix products
    float lpA1 = vA0, lpA2 = vA0 * vA1, lpA3 = lpA2 * vA2, totA = lpA3 * vA3;
    float lpB1 = vB0, lpB2 = vB0 * vB1, lpB3 = lpB2 * vB2, totB = lpB3 * vB3;

    // ---- interleaved warp scan-products (ILP=2) ----
    float pA = totA, pB = totB;
    #pragma unroll
    for (int off = 1; off < 32; off <<= 1) {
        float qA = __shfl_up_sync(FULL, pA, off);
        float qB = __shfl_up_sync(FULL, pB, off);
        if (lane >= off) { pA *= qA; pB *= qB; }
    }
    float exA = __shfl_up_sync(FULL, pA, 1);
    float exB = __shfl_up_sync(FULL, pB, 1);
    if (lane == 0) { exA = 1.0f; exB = 1.0f; }

    // ---- weights ----
    float TA0 = exA,        TA1 = exA * lpA1, TA2 = exA * lpA2, TA3 = exA * lpA3;
    float TB0 = exB,        TB1 = exB * lpB1, TB2 = exB * lpB2, TB3 = exB * lpB3;

    float wA0 = (TA0 > T_THRESH) ? aA0 * TA0 : 0.0f;
    float wA1 = (TA1 > T_THRESH) ? aA1 * TA1 : 0.0f;
    float wA2 = (TA2 > T_THRESH) ? aA2 * TA2 : 0.0f;
    float wA3 = (TA3 > T_THRESH) ? aA3 * TA3 : 0.0f;
    float wB0 = (TB0 > T_THRESH) ? aB0 * TB0 : 0.0f;
    float wB1 = (TB1 > T_THRESH) ? aB1 * TB1 : 0.0f;
    float wB2 = (TB2 > T_THRESH) ? aB2 * TB2 : 0.0f;
    float wB3 = (TB3 > T_THRESH) ? aB3 * TB3 : 0.0f;

    // ---- accumulate both rays ----
    float tbA = nearA + ((float)(4 * lane) + 0.5f) * dA;
    float tbB = nearB + ((float)(4 * lane) + 0.5f) * dB;

    float sA = wA0 + wA1 + wA2 + wA3;
    float sB = wB0 + wB1 + wB2 + wB3;
    float tA = wA0 * tbA + wA1 * (tbA + dA) + wA2 * (tbA + 2.0f * dA) + wA3 * (tbA + 3.0f * dA);
    float tB = wB0 * tbB + wB1 * (tbB + dB) + wB2 * (tbB + 2.0f * dB) + wB3 * (tbB + 3.0f * dB);

    float rA = wA0 * a0.x + wA1 * a0.w + wA2 * a1.z + wA3 * a2.y;
    float gA = wA0 * a0.y + wA1 * a1.x + wA2 * a1.w + wA3 * a2.z;
    float bA = wA0 * a0.z + wA1 * a1.y + wA2 * a2.x + wA3 * a2.w;
    float rB = wB0 * b0.x + wB1 * b0.w + wB2 * b1.z + wB3 * b2.y;
    float gB = wB0 * b0.y + wB1 * b1.x + wB2 * b1.w + wB3 * b2.z;
    float bB = wB0 * b0.z + wB1 * b1.y + wB2 * b2.x + wB3 * b2.w;

    // ---- interleaved butterfly reduction (10 values, ILP=10 per stage) ----
    #pragma unroll
    for (int off = 16; off > 0; off >>= 1) {
        sA += __shfl_xor_sync(FULL, sA, off);
        sB += __shfl_xor_sync(FULL, sB, off);
        tA += __shfl_xor_sync(FULL, tA, off);
        tB += __shfl_xor_sync(FULL, tB, off);
        rA += __shfl_xor_sync(FULL, rA, off);
        rB += __shfl_xor_sync(FULL, rB, off);
        gA += __shfl_xor_sync(FULL, gA, off);
        gB += __shfl_xor_sync(FULL, gB, off);
        bA += __shfl_xor_sync(FULL, bA, off);
        bB += __shfl_xor_sync(FULL, bB, off);
    }

    // lanes 0 and 1 write the two rays in parallel
    float* img   = out;
    float* depth = out + (size_t)3 * N;
    float* dnorm = out + (size_t)4 * N;

    if (lane == 0) {
        float bg = (1.0f - sA) * BG_COLOR;
        img[3 * r0 + 0] = rA + bg;
        img[3 * r0 + 1] = gA + bg;
        img[3 * r0 + 2] = bA + bg;
        depth[r0] = tA;
        dnorm[r0] = fmaxf(tA - nearA, 0.0f) / (farA - nearA);
    } else if (lane == 1 && r1 != r0) {
        float bg = (1.0f - sB) * BG_COLOR;
        img[3 * r1 + 0] = rB + bg;
        img[3 * r1 + 1] = gB + bg;
        img[3 * r1 + 2] = bB + bg;
        depth[r1] = tB;
        dnorm[r1] = fmaxf(tB - nearB, 0.0f) / (farB - nearB);
    }
}

extern "C" void kernel_launch(void* const* d_in, const int* in_sizes, int n_in,
                              void* d_out, int out_size)
{
    const float* rays_o = (const float*)d_in[0];
    const float* rays_d = (const float*)d_in[1];
    const float* sigmas = (const float*)d_in[2];
    const float* rgbs   = (const float*)d_in[3];
    float* out = (float*)d_out;

    int N = in_sizes[0] / 3;   // rays_o is [N,3]

    // one warp per 2 rays; 8 warps (256 threads) per block
    int rays_per_block = 2 * (256 / 32);
    int blocks = (N + rays_per_block - 1) / rays_per_block;
    nerf_composite_kernel<<<blocks, 256>>>(rays_o, rays_d, sigmas, rgbs, out, N);
}